// round 4
// baseline (speedup 1.0000x reference)
#include <cuda_runtime.h>

#define ND 32
#define MAXN 100000
#define MAXE 1600000

static constexpr size_t SLOT = (size_t)MAXN * ND;

// Scratch arena (floats):
//  T0,T1,X1,X2,h1,h2,fs,fd : 8 * SLOT
//  logit_c : MAXE ; csr_src : MAXE int ; csr_dst : MAXE int
//  tail: deg(N int), rs(N+1 int), cursor(N int), dinv(N f), blk(int), pad
__device__ float g_buf[8 * SLOT + 3 * (size_t)MAXE + 6 * (size_t)MAXN + 2048];

__device__ __forceinline__ float leaky(float x, float s) {
    return x > 0.0f ? x : s * x;
}

// ---------------------------------------------------------------------------
// degree + scan + CSR fill
// ---------------------------------------------------------------------------
__global__ void k_zero_i(int* __restrict__ p, int n) {
    int i = blockIdx.x * blockDim.x + threadIdx.x;
    if (i < n) p[i] = 0;
}

__global__ void k_deg(const int* __restrict__ dst, int* __restrict__ deg, int E) {
    int e = blockIdx.x * blockDim.x + threadIdx.x;
    if (e < E) atomicAdd(&deg[dst[e]], 1);
}

__global__ void k_dinv(const int* __restrict__ deg, float* __restrict__ dinv, int n) {
    int i = blockIdx.x * blockDim.x + threadIdx.x;
    if (i < n) dinv[i] = rsqrtf(fmaxf((float)deg[i], 1.0f));
}

// per-block exclusive scan (1024/block), block totals to blk[]
__global__ void k_scan1(const int* __restrict__ deg, int* __restrict__ rs,
                        int* __restrict__ blk, int n) {
    __shared__ int sh[1024];
    int i = blockIdx.x * 1024 + threadIdx.x;
    int v = (i < n) ? deg[i] : 0;
    sh[threadIdx.x] = v;
    __syncthreads();
#pragma unroll
    for (int o = 1; o < 1024; o <<= 1) {
        int t = (threadIdx.x >= o) ? sh[threadIdx.x - o] : 0;
        __syncthreads();
        sh[threadIdx.x] += t;
        __syncthreads();
    }
    if (i < n) rs[i] = sh[threadIdx.x] - v;  // exclusive
    if (threadIdx.x == 1023) blk[blockIdx.x] = sh[1023];
}

__global__ void k_scan2(int* __restrict__ blk, int nb) {
    if (threadIdx.x == 0 && blockIdx.x == 0) {
        int run = 0;
        for (int b = 0; b < nb; b++) { int t = blk[b]; blk[b] = run; run += t; }
    }
}

__global__ void k_scan3(int* __restrict__ rs, int* __restrict__ cursor,
                        const int* __restrict__ blk, int n, int E) {
    int i = blockIdx.x * blockDim.x + threadIdx.x;
    if (i < n) {
        int v = rs[i] + blk[i >> 10];
        rs[i] = v;
        cursor[i] = v;
    }
    if (i == 0) rs[n] = E;
}

__global__ void k_fill(const int* __restrict__ src, const int* __restrict__ dst,
                       int* __restrict__ cursor, int* __restrict__ csr_src,
                       int* __restrict__ csr_dst, int E) {
    int e = blockIdx.x * blockDim.x + threadIdx.x;
    if (e >= E) return;
    int d = dst[e];
    int p = atomicAdd(&cursor[d], 1);
    csr_src[p] = src[e];
    csr_dst[p] = d;
}

// ---------------------------------------------------------------------------
// node-parallel kernels
// ---------------------------------------------------------------------------
// T0 = f * dinv
__global__ void k_prescale(const float4* __restrict__ f, const float* __restrict__ dinv,
                           float4* __restrict__ T, int n) {
    int i = blockIdx.x * blockDim.x + threadIdx.x;
    if (i >= n * 8) return;
    float dv = dinv[i >> 3];
    float4 v = f[i];
    v.x *= dv; v.y *= dv; v.z *= dv; v.w *= dv;
    T[i] = v;
}

// warp-per-node CSR row sum with index prefetch + shfl broadcast
__device__ __forceinline__ float row_sum(const int* __restrict__ rs,
                                         const int* __restrict__ csr_src,
                                         const float* __restrict__ Tin,
                                         int v, int lane) {
    int beg = rs[v], end = rs[v + 1];
    float acc = 0.0f;
    for (int base = beg; base < end; base += 32) {
        int p = base + lane;
        int idx = (p < end) ? csr_src[p] : 0;
        int cnt = min(32, end - base);
#pragma unroll 8
        for (int j = 0; j < cnt; j++) {
            int sj = __shfl_sync(0xffffffffu, idx, j);
            acc += __ldg(Tin + (size_t)sj * ND + lane);
        }
    }
    return acc;
}

// X1 = -r*acc*dv + (r-1)*f; Tout = X1*dv
__global__ void k_chebA(const int* __restrict__ rs, const int* __restrict__ csr_src,
                        const float* __restrict__ Tin, const float* __restrict__ f,
                        const float* __restrict__ dinv, const float* __restrict__ lam,
                        float* __restrict__ X1, float* __restrict__ Tout, int n) {
    int v = blockIdx.x * 8 + threadIdx.y;
    if (v >= n) return;
    int lane = threadIdx.x;
    float acc = row_sum(rs, csr_src, Tin, v, lane);
    float r = 2.0f / lam[0];
    float dv = dinv[v];
    float x1 = -r * acc * dv + (r - 1.0f) * f[(size_t)v * ND + lane];
    X1[(size_t)v * ND + lane] = x1;
    Tout[(size_t)v * ND + lane] = x1 * dv;
}

// X2 = -2r*acc*dv + 2(r-1)*X1 - f
__global__ void k_chebB(const int* __restrict__ rs, const int* __restrict__ csr_src,
                        const float* __restrict__ Tin, const float* __restrict__ X1,
                        const float* __restrict__ f, const float* __restrict__ dinv,
                        const float* __restrict__ lam, float* __restrict__ X2, int n) {
    int v = blockIdx.x * 8 + threadIdx.y;
    if (v >= n) return;
    int lane = threadIdx.x;
    float acc = row_sum(rs, csr_src, Tin, v, lane);
    float r = 2.0f / lam[0];
    float dv = dinv[v];
    X2[(size_t)v * ND + lane] = -2.0f * r * acc * dv +
                                2.0f * (r - 1.0f) * X1[(size_t)v * ND + lane] -
                                f[(size_t)v * ND + lane];
}

// out = leaky_relu([X0,X1,X2] @ W + b, 0.01); optionally Tout = out*dinv
__global__ void k_cheb_linear(const float* __restrict__ X0, const float* __restrict__ X1,
                              const float* __restrict__ X2, const float* __restrict__ W,
                              const float* __restrict__ b, const float* __restrict__ dinv,
                              float* __restrict__ out, float* __restrict__ Tout, int n) {
    __shared__ float sW[96 * 32];
    __shared__ float sb[32];
    int t = threadIdx.y * 32 + threadIdx.x;
    for (int i = t; i < 96 * 32; i += 256) sW[i] = W[i];
    if (t < 32) sb[t] = b[t];
    __syncthreads();
    int node = blockIdx.x * 8 + threadIdx.y;
    if (node >= n) return;
    int col = threadIdx.x;
    float s = sb[col];
    const float* x0 = X0 + (size_t)node * ND;
    const float* x1 = X1 + (size_t)node * ND;
    const float* x2 = X2 + (size_t)node * ND;
#pragma unroll
    for (int j = 0; j < 32; j++) s += x0[j] * sW[j * 32 + col];
#pragma unroll
    for (int j = 0; j < 32; j++) s += x1[j] * sW[(32 + j) * 32 + col];
#pragma unroll
    for (int j = 0; j < 32; j++) s += x2[j] * sW[(64 + j) * 32 + col];
    s = leaky(s, 0.01f);
    out[(size_t)node * ND + col] = s;
    if (Tout) Tout[(size_t)node * ND + col] = s * dinv[node];
}

// fs = h@Ws+bs ; fd = h@Wd+bd
__global__ void k_fsfd(const float* __restrict__ h, const float* __restrict__ Ws,
                       const float* __restrict__ bs, const float* __restrict__ Wd,
                       const float* __restrict__ bd, float* __restrict__ fs,
                       float* __restrict__ fd, int n) {
    __shared__ float sWs[32 * 32], sWd[32 * 32], sbs[32], sbd[32];
    int t = threadIdx.y * 32 + threadIdx.x;
    for (int i = t; i < 1024; i += 256) { sWs[i] = Ws[i]; sWd[i] = Wd[i]; }
    if (t < 32) { sbs[t] = bs[t]; sbd[t] = bd[t]; }
    __syncthreads();
    int node = blockIdx.x * 8 + threadIdx.y;
    if (node >= n) return;
    int col = threadIdx.x;
    float a = sbs[col], c = sbd[col];
    const float* hr = h + (size_t)node * ND;
#pragma unroll
    for (int j = 0; j < 32; j++) {
        float x = hr[j];
        a += x * sWs[j * 32 + col];
        c += x * sWd[j * 32 + col];
    }
    fs[(size_t)node * ND + col] = a;
    fd[(size_t)node * ND + col] = c;
}

// edge-parallel logits in CSR order: 8 threads/edge, no atomics
__global__ void k_elog(const int* __restrict__ csr_src, const int* __restrict__ csr_dst,
                       const float4* __restrict__ fs, const float4* __restrict__ fd,
                       const float4* __restrict__ attn, float* __restrict__ logit_c,
                       int E) {
    long t = (long)blockIdx.x * blockDim.x + threadIdx.x;
    int p = (int)(t >> 3);
    if (p >= E) return;
    int lane = (int)(t & 7);
    int s = csr_src[p], d = csr_dst[p];
    float4 a = fs[(size_t)s * 8 + lane];
    float4 b = fd[(size_t)d * 8 + lane];
    float4 w = attn[lane];
    float v = leaky(a.x + b.x, 0.2f) * w.x + leaky(a.y + b.y, 0.2f) * w.y +
              leaky(a.z + b.z, 0.2f) * w.z + leaky(a.w + b.w, 0.2f) * w.w;
    v += __shfl_down_sync(0xffffffffu, v, 4, 8);
    v += __shfl_down_sync(0xffffffffu, v, 2, 8);
    v += __shfl_down_sync(0xffffffffu, v, 1, 8);
    if (lane == 0) logit_c[p] = v;
}

// warp per node: max + softmax + weighted aggregation + final leaky -> d_out
__global__ void k_gat2(const int* __restrict__ rs, const int* __restrict__ csr_src,
                       const float* __restrict__ fs, const float* __restrict__ logit_c,
                       float* __restrict__ out, int n) {
    int v = blockIdx.x * 8 + threadIdx.y;
    if (v >= n) return;
    int lane = threadIdx.x;
    int beg = rs[v], end = rs[v + 1];
    // pass 1: max over row (lane-parallel)
    float m = -3.0e38f;
    for (int base = beg; base < end; base += 32) {
        int p = base + lane;
        if (p < end) m = fmaxf(m, logit_c[p]);
    }
#pragma unroll
    for (int o = 16; o; o >>= 1) m = fmaxf(m, __shfl_xor_sync(0xffffffffu, m, o));
    // pass 2: exp + aggregate
    float acc = 0.0f, den = 0.0f;
    for (int base = beg; base < end; base += 32) {
        int p = base + lane;
        bool valid = p < end;
        int s = valid ? csr_src[p] : 0;
        float ex = valid ? expf(logit_c[p] - m) : 0.0f;
        den += ex;
        int cnt = min(32, end - base);
        for (int j = 0; j < cnt; j++) {
            float exj = __shfl_sync(0xffffffffu, ex, j);
            int sj = __shfl_sync(0xffffffffu, s, j);
            acc += __ldg(fs + (size_t)sj * ND + lane) * exj;
        }
    }
#pragma unroll
    for (int o = 16; o; o >>= 1) den += __shfl_xor_sync(0xffffffffu, den, o);
    float o = (den > 0.0f) ? leaky(acc / den, 0.01f) : 0.0f;
    out[(size_t)v * ND + lane] = o;
}

// ---------------------------------------------------------------------------
// launch
// ---------------------------------------------------------------------------
extern "C" void kernel_launch(void* const* d_in, const int* in_sizes, int n_in,
                              void* d_out, int out_size) {
    const int*   src  = (const int*)d_in[0];
    const int*   dst  = (const int*)d_in[1];
    const float* emb  = (const float*)d_in[2];
    const float* lam  = (const float*)d_in[3];
    const float* chW  = (const float*)d_in[4];
    const float* chb  = (const float*)d_in[5];
    const float* Ws   = (const float*)d_in[6];
    const float* bs   = (const float*)d_in[7];
    const float* Wd   = (const float*)d_in[8];
    const float* bd   = (const float*)d_in[9];
    const float* attn = (const float*)d_in[10];

    const int E = in_sizes[0];
    const int n = in_sizes[2] / ND;

    float* base = nullptr;
    cudaGetSymbolAddress((void**)&base, g_buf);

    float* T0      = base;
    float* T1      = base + 1 * SLOT;
    float* X1      = base + 2 * SLOT;
    float* X2      = base + 3 * SLOT;
    float* h1      = base + 4 * SLOT;
    float* h2      = base + 5 * SLOT;
    float* fs      = base + 6 * SLOT;
    float* fd      = base + 7 * SLOT;
    float* logit_c = base + 8 * SLOT;
    int*   csr_src = (int*)(logit_c + MAXE);
    int*   csr_dst = (int*)(logit_c + 2 * (size_t)MAXE);
    float* tail    = logit_c + 3 * (size_t)MAXE;
    int*   deg     = (int*)tail;
    int*   rs      = (int*)(tail + MAXN);          // N+1
    int*   cursor  = (int*)(tail + 2 * MAXN + 64);
    float* dinv    = tail + 3 * MAXN + 64;
    int*   blk     = (int*)(tail + 4 * MAXN + 64); // scan block sums

    const int nt = 256;
    auto g = [&](long x) { return (int)((x + nt - 1) / nt); };
    const int gV4   = g((long)n * 8);
    const int gE8   = g((long)E * 8);
    const int gEdge = g((long)E);
    const int gNW   = (n + 7) / 8;  // warp-per-node kernels
    dim3 bNW(32, 8);
    const int nb = (n + 1023) / 1024;

    // --- CSR build ---
    k_zero_i<<<g(n), nt>>>(deg, n);
    k_deg<<<gEdge, nt>>>(dst, deg, E);
    k_dinv<<<g(n), nt>>>(deg, dinv, n);
    k_scan1<<<nb, 1024>>>(deg, rs, blk, n);
    k_scan2<<<1, 32>>>(blk, nb);
    k_scan3<<<g(n), nt>>>(rs, cursor, blk, n, E);
    k_fill<<<gEdge, nt>>>(src, dst, cursor, csr_src, csr_dst, E);

    // --- ChebConv 1 (input = embedding) ---
    k_prescale<<<gV4, nt>>>((const float4*)emb, dinv, (float4*)T0, n);
    k_chebA<<<gNW, bNW>>>(rs, csr_src, T0, emb, dinv, lam, X1, T1, n);
    k_chebB<<<gNW, bNW>>>(rs, csr_src, T1, X1, emb, dinv, lam, X2, n);
    k_cheb_linear<<<gNW, bNW>>>(emb, X1, X2, chW, chb, dinv, h1, T0, n); // T0 = h1*dinv

    // --- ChebConv 2 (input = h1) ---
    k_chebA<<<gNW, bNW>>>(rs, csr_src, T0, h1, dinv, lam, X1, T1, n);
    k_chebB<<<gNW, bNW>>>(rs, csr_src, T1, X1, h1, dinv, lam, X2, n);
    k_cheb_linear<<<gNW, bNW>>>(h1, X1, X2, chW, chb, dinv, h2, nullptr, n);

    // --- GATv2 ---
    k_fsfd<<<gNW, bNW>>>(h2, Ws, bs, Wd, bd, fs, fd, n);
    k_elog<<<gE8, nt>>>(csr_src, csr_dst, (const float4*)fs, (const float4*)fd,
                        (const float4*)attn, logit_c, E);
    k_gat2<<<gNW, bNW>>>(rs, csr_src, fs, logit_c, (float*)d_out, n);
}

// round 5
// speedup vs baseline: 1.0535x; 1.0535x over previous
#include <cuda_runtime.h>

#define ND 32
#define MAXN 100000
#define MAXE 1600000

static constexpr size_t SLOT = (size_t)MAXN * ND;

// Scratch arena (floats):
//  T0,T1,X1,X2,h1,h2,fs,fd : 8 * SLOT
//  logit_c : MAXE ; csr_src : MAXE int ; csr_dst : MAXE int
//  tail: deg(N int), rs(N+1 int), cursor(N int), dinv(N f), blk(int), pad
__device__ float g_buf[8 * SLOT + 3 * (size_t)MAXE + 6 * (size_t)MAXN + 2048];

__device__ __forceinline__ float leaky(float x, float s) {
    return x > 0.0f ? x : s * x;
}

// ---------------------------------------------------------------------------
// degree + scan + CSR fill
// ---------------------------------------------------------------------------
__global__ void k_zero_i(int* __restrict__ p, int n) {
    int i = blockIdx.x * blockDim.x + threadIdx.x;
    if (i < n) p[i] = 0;
}

__global__ void k_deg(const int* __restrict__ dst, int* __restrict__ deg, int E) {
    int e = blockIdx.x * blockDim.x + threadIdx.x;
    if (e < E) atomicAdd(&deg[dst[e]], 1);
}

__global__ void k_dinv(const int* __restrict__ deg, float* __restrict__ dinv, int n) {
    int i = blockIdx.x * blockDim.x + threadIdx.x;
    if (i < n) dinv[i] = rsqrtf(fmaxf((float)deg[i], 1.0f));
}

// per-block exclusive scan (1024/block), block totals to blk[]
__global__ void k_scan1(const int* __restrict__ deg, int* __restrict__ rs,
                        int* __restrict__ blk, int n) {
    __shared__ int sh[1024];
    int i = blockIdx.x * 1024 + threadIdx.x;
    int v = (i < n) ? deg[i] : 0;
    sh[threadIdx.x] = v;
    __syncthreads();
#pragma unroll
    for (int o = 1; o < 1024; o <<= 1) {
        int t = (threadIdx.x >= o) ? sh[threadIdx.x - o] : 0;
        __syncthreads();
        sh[threadIdx.x] += t;
        __syncthreads();
    }
    if (i < n) rs[i] = sh[threadIdx.x] - v;  // exclusive
    if (threadIdx.x == 1023) blk[blockIdx.x] = sh[1023];
}

__global__ void k_scan2(int* __restrict__ blk, int nb) {
    if (threadIdx.x == 0 && blockIdx.x == 0) {
        int run = 0;
        for (int b = 0; b < nb; b++) { int t = blk[b]; blk[b] = run; run += t; }
    }
}

__global__ void k_scan3(int* __restrict__ rs, int* __restrict__ cursor,
                        const int* __restrict__ blk, int n, int E) {
    int i = blockIdx.x * blockDim.x + threadIdx.x;
    if (i < n) {
        int v = rs[i] + blk[i >> 10];
        rs[i] = v;
        cursor[i] = v;
    }
    if (i == 0) rs[n] = E;
}

__global__ void k_fill(const int* __restrict__ src, const int* __restrict__ dst,
                       int* __restrict__ cursor, int* __restrict__ csr_src,
                       int* __restrict__ csr_dst, int E) {
    int e = blockIdx.x * blockDim.x + threadIdx.x;
    if (e >= E) return;
    int d = dst[e];
    int p = atomicAdd(&cursor[d], 1);
    csr_src[p] = src[e];
    csr_dst[p] = d;
}

// ---------------------------------------------------------------------------
// node-parallel kernels
// ---------------------------------------------------------------------------
// T0 = f * dinv
__global__ void k_prescale(const float4* __restrict__ f, const float* __restrict__ dinv,
                           float4* __restrict__ T, int n) {
    int i = blockIdx.x * blockDim.x + threadIdx.x;
    if (i >= n * 8) return;
    float dv = dinv[i >> 3];
    float4 v = f[i];
    v.x *= dv; v.y *= dv; v.z *= dv; v.w *= dv;
    T[i] = v;
}

// warp-per-node CSR row sum, batched x8 for MLP (uniform index loads)
__device__ __forceinline__ float row_sum(const int* __restrict__ rs,
                                         const int* __restrict__ csr_src,
                                         const float* __restrict__ Tin,
                                         int v, int lane) {
    int beg = rs[v], end = rs[v + 1];
    float acc = 0.0f;
    int p = beg;
    for (; p + 8 <= end; p += 8) {
        int i0 = csr_src[p + 0], i1 = csr_src[p + 1];
        int i2 = csr_src[p + 2], i3 = csr_src[p + 3];
        int i4 = csr_src[p + 4], i5 = csr_src[p + 5];
        int i6 = csr_src[p + 6], i7 = csr_src[p + 7];
        float v0 = __ldg(Tin + (size_t)i0 * ND + lane);
        float v1 = __ldg(Tin + (size_t)i1 * ND + lane);
        float v2 = __ldg(Tin + (size_t)i2 * ND + lane);
        float v3 = __ldg(Tin + (size_t)i3 * ND + lane);
        float v4 = __ldg(Tin + (size_t)i4 * ND + lane);
        float v5 = __ldg(Tin + (size_t)i5 * ND + lane);
        float v6 = __ldg(Tin + (size_t)i6 * ND + lane);
        float v7 = __ldg(Tin + (size_t)i7 * ND + lane);
        acc += ((v0 + v1) + (v2 + v3)) + ((v4 + v5) + (v6 + v7));
    }
    for (; p < end; p++) acc += __ldg(Tin + (size_t)csr_src[p] * ND + lane);
    return acc;
}

// X1 = -r*acc*dv + (r-1)*f; Tout = X1*dv
__global__ void k_chebA(const int* __restrict__ rs, const int* __restrict__ csr_src,
                        const float* __restrict__ Tin, const float* __restrict__ f,
                        const float* __restrict__ dinv, const float* __restrict__ lam,
                        float* __restrict__ X1, float* __restrict__ Tout, int n) {
    int v = blockIdx.x * 8 + threadIdx.y;
    if (v >= n) return;
    int lane = threadIdx.x;
    float acc = row_sum(rs, csr_src, Tin, v, lane);
    float r = 2.0f / lam[0];
    float dv = dinv[v];
    float x1 = -r * acc * dv + (r - 1.0f) * f[(size_t)v * ND + lane];
    X1[(size_t)v * ND + lane] = x1;
    Tout[(size_t)v * ND + lane] = x1 * dv;
}

// X2 = -2r*acc*dv + 2(r-1)*X1 - f
__global__ void k_chebB(const int* __restrict__ rs, const int* __restrict__ csr_src,
                        const float* __restrict__ Tin, const float* __restrict__ X1,
                        const float* __restrict__ f, const float* __restrict__ dinv,
                        const float* __restrict__ lam, float* __restrict__ X2, int n) {
    int v = blockIdx.x * 8 + threadIdx.y;
    if (v >= n) return;
    int lane = threadIdx.x;
    float acc = row_sum(rs, csr_src, Tin, v, lane);
    float r = 2.0f / lam[0];
    float dv = dinv[v];
    X2[(size_t)v * ND + lane] = -2.0f * r * acc * dv +
                                2.0f * (r - 1.0f) * X1[(size_t)v * ND + lane] -
                                f[(size_t)v * ND + lane];
}

// out = leaky_relu([X0,X1,X2] @ W + b, 0.01); optionally Tout = out*dinv
__global__ void k_cheb_linear(const float* __restrict__ X0, const float* __restrict__ X1,
                              const float* __restrict__ X2, const float* __restrict__ W,
                              const float* __restrict__ b, const float* __restrict__ dinv,
                              float* __restrict__ out, float* __restrict__ Tout, int n) {
    __shared__ float sW[96 * 32];
    __shared__ float sb[32];
    int t = threadIdx.y * 32 + threadIdx.x;
    for (int i = t; i < 96 * 32; i += 256) sW[i] = W[i];
    if (t < 32) sb[t] = b[t];
    __syncthreads();
    int node = blockIdx.x * 8 + threadIdx.y;
    if (node >= n) return;
    int col = threadIdx.x;
    float s = sb[col];
    const float* x0 = X0 + (size_t)node * ND;
    const float* x1 = X1 + (size_t)node * ND;
    const float* x2 = X2 + (size_t)node * ND;
#pragma unroll
    for (int j = 0; j < 32; j++) s += x0[j] * sW[j * 32 + col];
#pragma unroll
    for (int j = 0; j < 32; j++) s += x1[j] * sW[(32 + j) * 32 + col];
#pragma unroll
    for (int j = 0; j < 32; j++) s += x2[j] * sW[(64 + j) * 32 + col];
    s = leaky(s, 0.01f);
    out[(size_t)node * ND + col] = s;
    if (Tout) Tout[(size_t)node * ND + col] = s * dinv[node];
}

// fs = h@Ws+bs ; fd = h@Wd+bd
__global__ void k_fsfd(const float* __restrict__ h, const float* __restrict__ Ws,
                       const float* __restrict__ bs, const float* __restrict__ Wd,
                       const float* __restrict__ bd, float* __restrict__ fs,
                       float* __restrict__ fd, int n) {
    __shared__ float sWs[32 * 32], sWd[32 * 32], sbs[32], sbd[32];
    int t = threadIdx.y * 32 + threadIdx.x;
    for (int i = t; i < 1024; i += 256) { sWs[i] = Ws[i]; sWd[i] = Wd[i]; }
    if (t < 32) { sbs[t] = bs[t]; sbd[t] = bd[t]; }
    __syncthreads();
    int node = blockIdx.x * 8 + threadIdx.y;
    if (node >= n) return;
    int col = threadIdx.x;
    float a = sbs[col], c = sbd[col];
    const float* hr = h + (size_t)node * ND;
#pragma unroll
    for (int j = 0; j < 32; j++) {
        float x = hr[j];
        a += x * sWs[j * 32 + col];
        c += x * sWd[j * 32 + col];
    }
    fs[(size_t)node * ND + col] = a;
    fd[(size_t)node * ND + col] = c;
}

// edge-parallel logits in CSR order: 8 threads/edge, no atomics
__global__ void k_elog(const int* __restrict__ csr_src, const int* __restrict__ csr_dst,
                       const float4* __restrict__ fs, const float4* __restrict__ fd,
                       const float4* __restrict__ attn, float* __restrict__ logit_c,
                       int E) {
    long t = (long)blockIdx.x * blockDim.x + threadIdx.x;
    int p = (int)(t >> 3);
    if (p >= E) return;
    int lane = (int)(t & 7);
    int s = csr_src[p], d = csr_dst[p];
    float4 a = fs[(size_t)s * 8 + lane];
    float4 b = fd[(size_t)d * 8 + lane];
    float4 w = attn[lane];
    float v = leaky(a.x + b.x, 0.2f) * w.x + leaky(a.y + b.y, 0.2f) * w.y +
              leaky(a.z + b.z, 0.2f) * w.z + leaky(a.w + b.w, 0.2f) * w.w;
    v += __shfl_down_sync(0xffffffffu, v, 4, 8);
    v += __shfl_down_sync(0xffffffffu, v, 2, 8);
    v += __shfl_down_sync(0xffffffffu, v, 1, 8);
    if (lane == 0) logit_c[p] = v;
}

// warp per node: max + softmax + weighted aggregation + final leaky -> d_out
__global__ void k_gat2(const int* __restrict__ rs, const int* __restrict__ csr_src,
                       const float* __restrict__ fs, const float* __restrict__ logit_c,
                       float* __restrict__ out, int n) {
    int v = blockIdx.x * 8 + threadIdx.y;
    if (v >= n) return;
    int lane = threadIdx.x;
    int beg = rs[v], end = rs[v + 1];
    // pass 1: max over row (lane-parallel)
    float m = -3.0e38f;
    for (int base = beg; base < end; base += 32) {
        int p = base + lane;
        if (p < end) m = fmaxf(m, logit_c[p]);
    }
#pragma unroll
    for (int o = 16; o; o >>= 1) m = fmaxf(m, __shfl_xor_sync(0xffffffffu, m, o));
    // pass 2: exp + aggregate, chunk-of-8 unrolled for MLP
    float acc = 0.0f, den = 0.0f;
    for (int base = beg; base < end; base += 32) {
        int p = base + lane;
        bool valid = p < end;
        int s = valid ? csr_src[p] : 0;
        float ex = valid ? expf(logit_c[p] - m) : 0.0f;
        den += ex;
        int cnt = min(32, end - base);
        int j = 0;
        for (; j + 8 <= cnt; j += 8) {
            int   s0 = __shfl_sync(0xffffffffu, s,  j + 0);
            int   s1 = __shfl_sync(0xffffffffu, s,  j + 1);
            int   s2 = __shfl_sync(0xffffffffu, s,  j + 2);
            int   s3 = __shfl_sync(0xffffffffu, s,  j + 3);
            int   s4 = __shfl_sync(0xffffffffu, s,  j + 4);
            int   s5 = __shfl_sync(0xffffffffu, s,  j + 5);
            int   s6 = __shfl_sync(0xffffffffu, s,  j + 6);
            int   s7 = __shfl_sync(0xffffffffu, s,  j + 7);
            float e0 = __shfl_sync(0xffffffffu, ex, j + 0);
            float e1 = __shfl_sync(0xffffffffu, ex, j + 1);
            float e2 = __shfl_sync(0xffffffffu, ex, j + 2);
            float e3 = __shfl_sync(0xffffffffu, ex, j + 3);
            float e4 = __shfl_sync(0xffffffffu, ex, j + 4);
            float e5 = __shfl_sync(0xffffffffu, ex, j + 5);
            float e6 = __shfl_sync(0xffffffffu, ex, j + 6);
            float e7 = __shfl_sync(0xffffffffu, ex, j + 7);
            float v0 = __ldg(fs + (size_t)s0 * ND + lane);
            float v1 = __ldg(fs + (size_t)s1 * ND + lane);
            float v2 = __ldg(fs + (size_t)s2 * ND + lane);
            float v3 = __ldg(fs + (size_t)s3 * ND + lane);
            float v4 = __ldg(fs + (size_t)s4 * ND + lane);
            float v5 = __ldg(fs + (size_t)s5 * ND + lane);
            float v6 = __ldg(fs + (size_t)s6 * ND + lane);
            float v7 = __ldg(fs + (size_t)s7 * ND + lane);
            acc += v0 * e0 + v1 * e1 + v2 * e2 + v3 * e3 +
                   v4 * e4 + v5 * e5 + v6 * e6 + v7 * e7;
        }
        for (; j < cnt; j++) {
            float exj = __shfl_sync(0xffffffffu, ex, j);
            int sj = __shfl_sync(0xffffffffu, s, j);
            acc += __ldg(fs + (size_t)sj * ND + lane) * exj;
        }
    }
#pragma unroll
    for (int o = 16; o; o >>= 1) den += __shfl_xor_sync(0xffffffffu, den, o);
    float o = (den > 0.0f) ? leaky(acc / den, 0.01f) : 0.0f;
    out[(size_t)v * ND + lane] = o;
}

// ---------------------------------------------------------------------------
// launch
// ---------------------------------------------------------------------------
extern "C" void kernel_launch(void* const* d_in, const int* in_sizes, int n_in,
                              void* d_out, int out_size) {
    const int*   src  = (const int*)d_in[0];
    const int*   dst  = (const int*)d_in[1];
    const float* emb  = (const float*)d_in[2];
    const float* lam  = (const float*)d_in[3];
    const float* chW  = (const float*)d_in[4];
    const float* chb  = (const float*)d_in[5];
    const float* Ws   = (const float*)d_in[6];
    const float* bs   = (const float*)d_in[7];
    const float* Wd   = (const float*)d_in[8];
    const float* bd   = (const float*)d_in[9];
    const float* attn = (const float*)d_in[10];

    const int E = in_sizes[0];
    const int n = in_sizes[2] / ND;

    float* base = nullptr;
    cudaGetSymbolAddress((void**)&base, g_buf);

    float* T0      = base;
    float* T1      = base + 1 * SLOT;
    float* X1      = base + 2 * SLOT;
    float* X2      = base + 3 * SLOT;
    float* h1      = base + 4 * SLOT;
    float* h2      = base + 5 * SLOT;
    float* fs      = base + 6 * SLOT;
    float* fd      = base + 7 * SLOT;
    float* logit_c = base + 8 * SLOT;
    int*   csr_src = (int*)(logit_c + MAXE);
    int*   csr_dst = (int*)(logit_c + 2 * (size_t)MAXE);
    float* tail    = logit_c + 3 * (size_t)MAXE;
    int*   deg     = (int*)tail;
    int*   rs      = (int*)(tail + MAXN);          // N+1
    int*   cursor  = (int*)(tail + 2 * MAXN + 64);
    float* dinv    = tail + 3 * MAXN + 64;
    int*   blk     = (int*)(tail + 4 * MAXN + 64); // scan block sums

    const int nt = 256;
    auto g = [&](long x) { return (int)((x + nt - 1) / nt); };
    const int gV4   = g((long)n * 8);
    const int gE8   = g((long)E * 8);
    const int gEdge = g((long)E);
    const int gNW   = (n + 7) / 8;  // warp-per-node kernels
    dim3 bNW(32, 8);
    const int nb = (n + 1023) / 1024;

    // --- CSR build ---
    k_zero_i<<<g(n), nt>>>(deg, n);
    k_deg<<<gEdge, nt>>>(dst, deg, E);
    k_dinv<<<g(n), nt>>>(deg, dinv, n);
    k_scan1<<<nb, 1024>>>(deg, rs, blk, n);
    k_scan2<<<1, 32>>>(blk, nb);
    k_scan3<<<g(n), nt>>>(rs, cursor, blk, n, E);
    k_fill<<<gEdge, nt>>>(src, dst, cursor, csr_src, csr_dst, E);

    // --- ChebConv 1 (input = embedding) ---
    k_prescale<<<gV4, nt>>>((const float4*)emb, dinv, (float4*)T0, n);
    k_chebA<<<gNW, bNW>>>(rs, csr_src, T0, emb, dinv, lam, X1, T1, n);
    k_chebB<<<gNW, bNW>>>(rs, csr_src, T1, X1, emb, dinv, lam, X2, n);
    k_cheb_linear<<<gNW, bNW>>>(emb, X1, X2, chW, chb, dinv, h1, T0, n); // T0 = h1*dinv

    // --- ChebConv 2 (input = h1) ---
    k_chebA<<<gNW, bNW>>>(rs, csr_src, T0, h1, dinv, lam, X1, T1, n);
    k_chebB<<<gNW, bNW>>>(rs, csr_src, T1, X1, h1, dinv, lam, X2, n);
    k_cheb_linear<<<gNW, bNW>>>(h1, X1, X2, chW, chb, dinv, h2, nullptr, n);

    // --- GATv2 ---
    k_fsfd<<<gNW, bNW>>>(h2, Ws, bs, Wd, bd, fs, fd, n);
    k_elog<<<gE8, nt>>>(csr_src, csr_dst, (const float4*)fs, (const float4*)fd,
                        (const float4*)attn, logit_c, E);
    k_gat2<<<gNW, bNW>>>(rs, csr_src, fs, logit_c, (float*)d_out, n);
}

// round 6
// speedup vs baseline: 1.1055x; 1.0494x over previous
#include <cuda_runtime.h>

#define ND 32
#define MAXN 100000
#define MAXE 1600000

static constexpr size_t SLOT = (size_t)MAXN * ND;

// Scratch arena (floats):
//  T0,T1,X1,X2,h1,h2,fs,fd : 8 * SLOT
//  logit_c : MAXE ; csr_src : MAXE int ; csr_dst : MAXE int
//  tail: deg(N int), rs(N+1 int), cursor(N int), dinv(N f), blk(int), pad
__device__ __align__(256) float g_buf[8 * SLOT + 3 * (size_t)MAXE + 6 * (size_t)MAXN + 2048];

__device__ __forceinline__ float leaky(float x, float s) {
    return x > 0.0f ? x : s * x;
}

// ---------------------------------------------------------------------------
// degree + scan + CSR fill
// ---------------------------------------------------------------------------
__global__ void k_zero_i(int* __restrict__ p, int n) {
    int i = blockIdx.x * blockDim.x + threadIdx.x;
    if (i < n) p[i] = 0;
}

__global__ void k_deg(const int* __restrict__ dst, int* __restrict__ deg, int E) {
    int e = blockIdx.x * blockDim.x + threadIdx.x;
    if (e < E) atomicAdd(&deg[dst[e]], 1);
}

// per-block exclusive scan (1024/block), block totals to blk[]
__global__ void k_scan1(const int* __restrict__ deg, int* __restrict__ rs,
                        int* __restrict__ blk, int n) {
    __shared__ int sh[1024];
    int i = blockIdx.x * 1024 + threadIdx.x;
    int v = (i < n) ? deg[i] : 0;
    sh[threadIdx.x] = v;
    __syncthreads();
#pragma unroll
    for (int o = 1; o < 1024; o <<= 1) {
        int t = (threadIdx.x >= o) ? sh[threadIdx.x - o] : 0;
        __syncthreads();
        sh[threadIdx.x] += t;
        __syncthreads();
    }
    if (i < n) rs[i] = sh[threadIdx.x] - v;  // exclusive
    if (threadIdx.x == 1023) blk[blockIdx.x] = sh[1023];
}

// parallel exclusive scan of block sums (nb <= 128)
__global__ void k_scan2(int* __restrict__ blk, int nb) {
    __shared__ int sh[128];
    int t = threadIdx.x;
    int v = (t < nb) ? blk[t] : 0;
    sh[t] = v;
    __syncthreads();
#pragma unroll
    for (int o = 1; o < 128; o <<= 1) {
        int x = (t >= o) ? sh[t - o] : 0;
        __syncthreads();
        sh[t] += x;
        __syncthreads();
    }
    if (t < nb) blk[t] = sh[t] - v;  // exclusive
}

// finalize row starts + cursors + dinv
__global__ void k_scan3(int* __restrict__ rs, int* __restrict__ cursor,
                        const int* __restrict__ blk, const int* __restrict__ deg,
                        float* __restrict__ dinv, int n, int E) {
    int i = blockIdx.x * blockDim.x + threadIdx.x;
    if (i < n) {
        int v = rs[i] + blk[i >> 10];
        rs[i] = v;
        cursor[i] = v;
        dinv[i] = rsqrtf(fmaxf((float)deg[i], 1.0f));
    }
    if (i == 0) rs[n] = E;
}

__global__ void k_fill(const int* __restrict__ src, const int* __restrict__ dst,
                       int* __restrict__ cursor, int* __restrict__ csr_src,
                       int* __restrict__ csr_dst, int E) {
    int e = blockIdx.x * blockDim.x + threadIdx.x;
    if (e >= E) return;
    int d = dst[e];
    int p = atomicAdd(&cursor[d], 1);
    csr_src[p] = src[e];
    csr_dst[p] = d;
}

// ---------------------------------------------------------------------------
// node-parallel kernels
// ---------------------------------------------------------------------------
// T0 = f * dinv
__global__ void k_prescale(const float4* __restrict__ f, const float* __restrict__ dinv,
                           float4* __restrict__ T, int n) {
    int i = blockIdx.x * blockDim.x + threadIdx.x;
    if (i >= n * 8) return;
    float dv = dinv[i >> 3];
    float4 v = f[i];
    v.x *= dv; v.y *= dv; v.z *= dv; v.w *= dv;
    T[i] = v;
}

// warp-per-node CSR row sum: 4 edges x 8 lanes (float4), cross-group shfl reduce.
// Returns full-row sum as float4; lanes with same (lane&7) hold the same value.
__device__ __forceinline__ float4 row_sum4(int beg, int end,
                                           const int* __restrict__ csr_src,
                                           const float4* __restrict__ Tin,
                                           int g, int c) {
    float4 acc = make_float4(0.f, 0.f, 0.f, 0.f);
    int base = beg;
    for (; base + 8 <= end; base += 8) {
        int i0 = __ldg(csr_src + base + g);
        int i1 = __ldg(csr_src + base + 4 + g);
        float4 v0 = __ldg(Tin + (size_t)i0 * 8 + c);
        float4 v1 = __ldg(Tin + (size_t)i1 * 8 + c);
        acc.x += v0.x + v1.x;
        acc.y += v0.y + v1.y;
        acc.z += v0.z + v1.z;
        acc.w += v0.w + v1.w;
    }
    for (; base < end; base += 4) {
        int p = base + g;
        if (p < end) {
            int i0 = __ldg(csr_src + p);
            float4 v0 = __ldg(Tin + (size_t)i0 * 8 + c);
            acc.x += v0.x; acc.y += v0.y; acc.z += v0.z; acc.w += v0.w;
        }
    }
    // reduce across the 4 groups (lanes 8 and 16 apart)
#pragma unroll
    for (int o = 8; o <= 16; o <<= 1) {
        acc.x += __shfl_xor_sync(0xffffffffu, acc.x, o);
        acc.y += __shfl_xor_sync(0xffffffffu, acc.y, o);
        acc.z += __shfl_xor_sync(0xffffffffu, acc.z, o);
        acc.w += __shfl_xor_sync(0xffffffffu, acc.w, o);
    }
    return acc;
}

// X1 = -r*acc*dv + (r-1)*f; Tout = X1*dv
__global__ void k_chebA(const int* __restrict__ rs, const int* __restrict__ csr_src,
                        const float4* __restrict__ Tin, const float4* __restrict__ f,
                        const float* __restrict__ dinv, const float* __restrict__ lam,
                        float4* __restrict__ X1, float4* __restrict__ Tout, int n) {
    int v = blockIdx.x * 8 + threadIdx.y;
    if (v >= n) return;
    int lane = threadIdx.x;
    int g = lane >> 3, c = lane & 7;
    int beg = rs[v], end = rs[v + 1];
    float4 acc = row_sum4(beg, end, csr_src, Tin, g, c);
    if (g == 0) {
        float r = 2.0f / lam[0];
        float dv = dinv[v];
        float4 f4 = __ldg(f + (size_t)v * 8 + c);
        float4 x1;
        x1.x = -r * acc.x * dv + (r - 1.0f) * f4.x;
        x1.y = -r * acc.y * dv + (r - 1.0f) * f4.y;
        x1.z = -r * acc.z * dv + (r - 1.0f) * f4.z;
        x1.w = -r * acc.w * dv + (r - 1.0f) * f4.w;
        X1[(size_t)v * 8 + c] = x1;
        float4 t;
        t.x = x1.x * dv; t.y = x1.y * dv; t.z = x1.z * dv; t.w = x1.w * dv;
        Tout[(size_t)v * 8 + c] = t;
    }
}

// X2 = -2r*acc*dv + 2(r-1)*X1 - f
__global__ void k_chebB(const int* __restrict__ rs, const int* __restrict__ csr_src,
                        const float4* __restrict__ Tin, const float4* __restrict__ X1,
                        const float4* __restrict__ f, const float* __restrict__ dinv,
                        const float* __restrict__ lam, float4* __restrict__ X2, int n) {
    int v = blockIdx.x * 8 + threadIdx.y;
    if (v >= n) return;
    int lane = threadIdx.x;
    int g = lane >> 3, c = lane & 7;
    int beg = rs[v], end = rs[v + 1];
    float4 acc = row_sum4(beg, end, csr_src, Tin, g, c);
    if (g == 0) {
        float r = 2.0f / lam[0];
        float dv = dinv[v];
        float4 x1 = __ldg(X1 + (size_t)v * 8 + c);
        float4 f4 = __ldg(f + (size_t)v * 8 + c);
        float4 o;
        o.x = -2.0f * r * acc.x * dv + 2.0f * (r - 1.0f) * x1.x - f4.x;
        o.y = -2.0f * r * acc.y * dv + 2.0f * (r - 1.0f) * x1.y - f4.y;
        o.z = -2.0f * r * acc.z * dv + 2.0f * (r - 1.0f) * x1.z - f4.z;
        o.w = -2.0f * r * acc.w * dv + 2.0f * (r - 1.0f) * x1.w - f4.w;
        X2[(size_t)v * 8 + c] = o;
    }
}

// out = leaky_relu([X0,X1,X2] @ W + b, 0.01); optionally Tout = out*dinv
__global__ void k_cheb_linear(const float* __restrict__ X0, const float* __restrict__ X1,
                              const float* __restrict__ X2, const float* __restrict__ W,
                              const float* __restrict__ b, const float* __restrict__ dinv,
                              float* __restrict__ out, float* __restrict__ Tout, int n) {
    __shared__ float sW[96 * 32];
    __shared__ float sb[32];
    int t = threadIdx.y * 32 + threadIdx.x;
    for (int i = t; i < 96 * 32; i += 256) sW[i] = W[i];
    if (t < 32) sb[t] = b[t];
    __syncthreads();
    int node = blockIdx.x * 8 + threadIdx.y;
    if (node >= n) return;
    int col = threadIdx.x;
    float s = sb[col];
    const float* x0 = X0 + (size_t)node * ND;
    const float* x1 = X1 + (size_t)node * ND;
    const float* x2 = X2 + (size_t)node * ND;
#pragma unroll
    for (int j = 0; j < 32; j++) s += x0[j] * sW[j * 32 + col];
#pragma unroll
    for (int j = 0; j < 32; j++) s += x1[j] * sW[(32 + j) * 32 + col];
#pragma unroll
    for (int j = 0; j < 32; j++) s += x2[j] * sW[(64 + j) * 32 + col];
    s = leaky(s, 0.01f);
    out[(size_t)node * ND + col] = s;
    if (Tout) Tout[(size_t)node * ND + col] = s * dinv[node];
}

// fs = h@Ws+bs ; fd = h@Wd+bd
__global__ void k_fsfd(const float* __restrict__ h, const float* __restrict__ Ws,
                       const float* __restrict__ bs, const float* __restrict__ Wd,
                       const float* __restrict__ bd, float* __restrict__ fs,
                       float* __restrict__ fd, int n) {
    __shared__ float sWs[32 * 32], sWd[32 * 32], sbs[32], sbd[32];
    int t = threadIdx.y * 32 + threadIdx.x;
    for (int i = t; i < 1024; i += 256) { sWs[i] = Ws[i]; sWd[i] = Wd[i]; }
    if (t < 32) { sbs[t] = bs[t]; sbd[t] = bd[t]; }
    __syncthreads();
    int node = blockIdx.x * 8 + threadIdx.y;
    if (node >= n) return;
    int col = threadIdx.x;
    float a = sbs[col], c = sbd[col];
    const float* hr = h + (size_t)node * ND;
#pragma unroll
    for (int j = 0; j < 32; j++) {
        float x = hr[j];
        a += x * sWs[j * 32 + col];
        c += x * sWd[j * 32 + col];
    }
    fs[(size_t)node * ND + col] = a;
    fd[(size_t)node * ND + col] = c;
}

// edge-parallel logits in CSR order: 8 threads/edge, no atomics
__global__ void k_elog(const int* __restrict__ csr_src, const int* __restrict__ csr_dst,
                       const float4* __restrict__ fs, const float4* __restrict__ fd,
                       const float4* __restrict__ attn, float* __restrict__ logit_c,
                       int E) {
    long t = (long)blockIdx.x * blockDim.x + threadIdx.x;
    int p = (int)(t >> 3);
    if (p >= E) return;
    int lane = (int)(t & 7);
    int s = csr_src[p], d = csr_dst[p];
    float4 a = fs[(size_t)s * 8 + lane];
    float4 b = fd[(size_t)d * 8 + lane];
    float4 w = attn[lane];
    float v = leaky(a.x + b.x, 0.2f) * w.x + leaky(a.y + b.y, 0.2f) * w.y +
              leaky(a.z + b.z, 0.2f) * w.z + leaky(a.w + b.w, 0.2f) * w.w;
    v += __shfl_down_sync(0xffffffffu, v, 4, 8);
    v += __shfl_down_sync(0xffffffffu, v, 2, 8);
    v += __shfl_down_sync(0xffffffffu, v, 1, 8);
    if (lane == 0) logit_c[p] = v;
}

// warp per node: max + softmax + weighted aggregation + final leaky -> d_out
// aggregation uses 4 edges x 8 lanes (float4 rows)
__global__ void k_gat2(const int* __restrict__ rs, const int* __restrict__ csr_src,
                       const float4* __restrict__ fs, const float* __restrict__ logit_c,
                       float4* __restrict__ out, int n) {
    int v = blockIdx.x * 8 + threadIdx.y;
    if (v >= n) return;
    int lane = threadIdx.x;
    int g = lane >> 3, c = lane & 7;
    int beg = rs[v], end = rs[v + 1];
    // pass 1: max over row (lane-parallel, coalesced)
    float m = -3.0e38f;
    for (int base = beg; base < end; base += 32) {
        int p = base + lane;
        if (p < end) m = fmaxf(m, logit_c[p]);
    }
#pragma unroll
    for (int o = 16; o; o >>= 1) m = fmaxf(m, __shfl_xor_sync(0xffffffffu, m, o));
    // pass 2: exp + aggregate, group-of-8 float4 edges
    float4 acc = make_float4(0.f, 0.f, 0.f, 0.f);
    float den = 0.0f;
    int base = beg;
    for (; base + 8 <= end; base += 8) {
        int p0 = base + g, p1 = base + 4 + g;
        int i0 = __ldg(csr_src + p0);
        int i1 = __ldg(csr_src + p1);
        float e0 = expf(__ldg(logit_c + p0) - m);
        float e1 = expf(__ldg(logit_c + p1) - m);
        float4 v0 = __ldg(fs + (size_t)i0 * 8 + c);
        float4 v1 = __ldg(fs + (size_t)i1 * 8 + c);
        acc.x += v0.x * e0 + v1.x * e1;
        acc.y += v0.y * e0 + v1.y * e1;
        acc.z += v0.z * e0 + v1.z * e1;
        acc.w += v0.w * e0 + v1.w * e1;
        if (c == 0) den += e0 + e1;
    }
    for (; base < end; base += 4) {
        int p = base + g;
        if (p < end) {
            int i0 = __ldg(csr_src + p);
            float e0 = expf(__ldg(logit_c + p) - m);
            float4 v0 = __ldg(fs + (size_t)i0 * 8 + c);
            acc.x += v0.x * e0; acc.y += v0.y * e0;
            acc.z += v0.z * e0; acc.w += v0.w * e0;
            if (c == 0) den += e0;
        }
    }
    // reduce across the 4 groups
#pragma unroll
    for (int o = 8; o <= 16; o <<= 1) {
        acc.x += __shfl_xor_sync(0xffffffffu, acc.x, o);
        acc.y += __shfl_xor_sync(0xffffffffu, acc.y, o);
        acc.z += __shfl_xor_sync(0xffffffffu, acc.z, o);
        acc.w += __shfl_xor_sync(0xffffffffu, acc.w, o);
        den   += __shfl_xor_sync(0xffffffffu, den,   o);
    }
    den = __shfl_sync(0xffffffffu, den, 0);  // lanes with c==0 summed; lane0 has full den
    if (g == 0) {
        float inv = (den > 0.0f) ? 1.0f / den : 0.0f;
        float4 o;
        o.x = leaky(acc.x * inv, 0.01f);
        o.y = leaky(acc.y * inv, 0.01f);
        o.z = leaky(acc.z * inv, 0.01f);
        o.w = leaky(acc.w * inv, 0.01f);
        out[(size_t)v * 8 + c] = o;
    }
}

// ---------------------------------------------------------------------------
// launch
// ---------------------------------------------------------------------------
extern "C" void kernel_launch(void* const* d_in, const int* in_sizes, int n_in,
                              void* d_out, int out_size) {
    const int*   src  = (const int*)d_in[0];
    const int*   dst  = (const int*)d_in[1];
    const float* emb  = (const float*)d_in[2];
    const float* lam  = (const float*)d_in[3];
    const float* chW  = (const float*)d_in[4];
    const float* chb  = (const float*)d_in[5];
    const float* Ws   = (const float*)d_in[6];
    const float* bs   = (const float*)d_in[7];
    const float* Wd   = (const float*)d_in[8];
    const float* bd   = (const float*)d_in[9];
    const float* attn = (const float*)d_in[10];

    const int E = in_sizes[0];
    const int n = in_sizes[2] / ND;

    float* base = nullptr;
    cudaGetSymbolAddress((void**)&base, g_buf);

    float* T0      = base;
    float* T1      = base + 1 * SLOT;
    float* X1      = base + 2 * SLOT;
    float* X2      = base + 3 * SLOT;
    float* h1      = base + 4 * SLOT;
    float* h2      = base + 5 * SLOT;
    float* fs      = base + 6 * SLOT;
    float* fd      = base + 7 * SLOT;
    float* logit_c = base + 8 * SLOT;
    int*   csr_src = (int*)(logit_c + MAXE);
    int*   csr_dst = (int*)(logit_c + 2 * (size_t)MAXE);
    float* tail    = logit_c + 3 * (size_t)MAXE;
    int*   deg     = (int*)tail;
    int*   rs      = (int*)(tail + MAXN);          // N+1
    int*   cursor  = (int*)(tail + 2 * MAXN + 64);
    float* dinv    = tail + 3 * MAXN + 64;
    int*   blk     = (int*)(tail + 4 * MAXN + 64); // scan block sums

    const int nt = 256;
    auto g = [&](long x) { return (int)((x + nt - 1) / nt); };
    const int gV4   = g((long)n * 8);
    const int gE8   = g((long)E * 8);
    const int gEdge = g((long)E);
    const int gNW   = (n + 7) / 8;  // warp-per-node kernels
    dim3 bNW(32, 8);
    const int nb = (n + 1023) / 1024;

    // --- CSR build ---
    k_zero_i<<<g(n), nt>>>(deg, n);
    k_deg<<<gEdge, nt>>>(dst, deg, E);
    k_scan1<<<nb, 1024>>>(deg, rs, blk, n);
    k_scan2<<<1, 128>>>(blk, nb);
    k_scan3<<<g(n), nt>>>(rs, cursor, blk, deg, dinv, n, E);
    k_fill<<<gEdge, nt>>>(src, dst, cursor, csr_src, csr_dst, E);

    // --- ChebConv 1 (input = embedding) ---
    k_prescale<<<gV4, nt>>>((const float4*)emb, dinv, (float4*)T0, n);
    k_chebA<<<gNW, bNW>>>(rs, csr_src, (const float4*)T0, (const float4*)emb,
                          dinv, lam, (float4*)X1, (float4*)T1, n);
    k_chebB<<<gNW, bNW>>>(rs, csr_src, (const float4*)T1, (const float4*)X1,
                          (const float4*)emb, dinv, lam, (float4*)X2, n);
    k_cheb_linear<<<gNW, bNW>>>(emb, X1, X2, chW, chb, dinv, h1, T0, n); // T0 = h1*dinv

    // --- ChebConv 2 (input = h1) ---
    k_chebA<<<gNW, bNW>>>(rs, csr_src, (const float4*)T0, (const float4*)h1,
                          dinv, lam, (float4*)X1, (float4*)T1, n);
    k_chebB<<<gNW, bNW>>>(rs, csr_src, (const float4*)T1, (const float4*)X1,
                          (const float4*)h1, dinv, lam, (float4*)X2, n);
    k_cheb_linear<<<gNW, bNW>>>(h1, X1, X2, chW, chb, dinv, h2, nullptr, n);

    // --- GATv2 ---
    k_fsfd<<<gNW, bNW>>>(h2, Ws, bs, Wd, bd, fs, fd, n);
    k_elog<<<gE8, nt>>>(csr_src, csr_dst, (const float4*)fs, (const float4*)fd,
                        (const float4*)attn, logit_c, E);
    k_gat2<<<gNW, bNW>>>(rs, csr_src, (const float4*)fs, logit_c,
                         (float4*)d_out, n);
}

// round 7
// speedup vs baseline: 1.2387x; 1.1204x over previous
#include <cuda_runtime.h>
#include <cuda_fp16.h>

#define ND 32
#define MAXN 100000
#define MAXE 1600000

static constexpr size_t SLOT = (size_t)MAXN * ND;

// Scratch arena (floats):
//  X1,X2,h1,h2,fs,fd : 6 * SLOT fp32
//  T0h,T1h : 2 * SLOT/2 (fp16 rows, N*32 halves each)
//  csr_src : MAXE int
//  tail: deg(N), rs(N+1), cursor(N), dinv(N), blk(128)
__device__ __align__(256) float g_buf[7 * SLOT + (size_t)MAXE + 6 * (size_t)MAXN + 2048];

__device__ __forceinline__ float leaky(float x, float s) {
    return x > 0.0f ? x : s * x;
}
__device__ __forceinline__ uint2 f4_to_h4(float4 v) {
    __half2 a = __floats2half2_rn(v.x, v.y);
    __half2 b = __floats2half2_rn(v.z, v.w);
    uint2 r;
    r.x = *(unsigned*)&a;
    r.y = *(unsigned*)&b;
    return r;
}
__device__ __forceinline__ float4 h4_to_f4(uint2 u) {
    __half2 a = *(__half2*)&u.x;
    __half2 b = *(__half2*)&u.y;
    float2 fa = __half22float2(a), fb = __half22float2(b);
    return make_float4(fa.x, fa.y, fb.x, fb.y);
}

// ---------------------------------------------------------------------------
// degree + scan + CSR fill
// ---------------------------------------------------------------------------
__global__ void k_zero_i(int* __restrict__ p, int n) {
    int i = blockIdx.x * blockDim.x + threadIdx.x;
    if (i < n) p[i] = 0;
}

__global__ void k_deg(const int* __restrict__ dst, int* __restrict__ deg, int E) {
    int e = blockIdx.x * blockDim.x + threadIdx.x;
    if (e < E) atomicAdd(&deg[dst[e]], 1);
}

__global__ void k_scan1(const int* __restrict__ deg, int* __restrict__ rs,
                        int* __restrict__ blk, int n) {
    __shared__ int sh[1024];
    int i = blockIdx.x * 1024 + threadIdx.x;
    int v = (i < n) ? deg[i] : 0;
    sh[threadIdx.x] = v;
    __syncthreads();
#pragma unroll
    for (int o = 1; o < 1024; o <<= 1) {
        int t = (threadIdx.x >= o) ? sh[threadIdx.x - o] : 0;
        __syncthreads();
        sh[threadIdx.x] += t;
        __syncthreads();
    }
    if (i < n) rs[i] = sh[threadIdx.x] - v;
    if (threadIdx.x == 1023) blk[blockIdx.x] = sh[1023];
}

__global__ void k_scan2(int* __restrict__ blk, int nb) {
    __shared__ int sh[128];
    int t = threadIdx.x;
    int v = (t < nb) ? blk[t] : 0;
    sh[t] = v;
    __syncthreads();
#pragma unroll
    for (int o = 1; o < 128; o <<= 1) {
        int x = (t >= o) ? sh[t - o] : 0;
        __syncthreads();
        sh[t] += x;
        __syncthreads();
    }
    if (t < nb) blk[t] = sh[t] - v;
}

__global__ void k_scan3(int* __restrict__ rs, int* __restrict__ cursor,
                        const int* __restrict__ blk, const int* __restrict__ deg,
                        float* __restrict__ dinv, int n, int E) {
    int i = blockIdx.x * blockDim.x + threadIdx.x;
    if (i < n) {
        int v = rs[i] + blk[i >> 10];
        rs[i] = v;
        cursor[i] = v;
        dinv[i] = rsqrtf(fmaxf((float)deg[i], 1.0f));
    }
    if (i == 0) rs[n] = E;
}

__global__ void k_fill(const int* __restrict__ src, const int* __restrict__ dst,
                       int* __restrict__ cursor, int* __restrict__ csr_src, int E) {
    int e = blockIdx.x * blockDim.x + threadIdx.x;
    if (e >= E) return;
    int p = atomicAdd(&cursor[dst[e]], 1);
    csr_src[p] = src[e];
}

// ---------------------------------------------------------------------------
// Cheb kernels
// ---------------------------------------------------------------------------
// T0h = half(f * dinv)
__global__ void k_prescale(const float4* __restrict__ f, const float* __restrict__ dinv,
                           uint2* __restrict__ Th, int n) {
    int i = blockIdx.x * blockDim.x + threadIdx.x;
    if (i >= n * 8) return;
    float dv = dinv[i >> 3];
    float4 v = f[i];
    v.x *= dv; v.y *= dv; v.z *= dv; v.w *= dv;
    Th[i] = f4_to_h4(v);
}

// warp-per-node CSR row sum over fp16 rows: 4 edges x 8 lanes, fp32 accum
__device__ __forceinline__ float4 row_sum4h(int beg, int end,
                                            const int* __restrict__ csr_src,
                                            const uint2* __restrict__ Th,
                                            int g, int c) {
    float4 acc = make_float4(0.f, 0.f, 0.f, 0.f);
    int base = beg;
    for (; base + 8 <= end; base += 8) {
        int i0 = __ldg(csr_src + base + g);
        int i1 = __ldg(csr_src + base + 4 + g);
        float4 v0 = h4_to_f4(__ldg(Th + (size_t)i0 * 8 + c));
        float4 v1 = h4_to_f4(__ldg(Th + (size_t)i1 * 8 + c));
        acc.x += v0.x + v1.x;
        acc.y += v0.y + v1.y;
        acc.z += v0.z + v1.z;
        acc.w += v0.w + v1.w;
    }
    for (; base < end; base += 4) {
        int p = base + g;
        if (p < end) {
            int i0 = __ldg(csr_src + p);
            float4 v0 = h4_to_f4(__ldg(Th + (size_t)i0 * 8 + c));
            acc.x += v0.x; acc.y += v0.y; acc.z += v0.z; acc.w += v0.w;
        }
    }
#pragma unroll
    for (int o = 8; o <= 16; o <<= 1) {
        acc.x += __shfl_xor_sync(0xffffffffu, acc.x, o);
        acc.y += __shfl_xor_sync(0xffffffffu, acc.y, o);
        acc.z += __shfl_xor_sync(0xffffffffu, acc.z, o);
        acc.w += __shfl_xor_sync(0xffffffffu, acc.w, o);
    }
    return acc;
}

// X1 = -r*acc*dv + (r-1)*f; T1h = half(X1*dv)
__global__ void k_chebA(const int* __restrict__ rs, const int* __restrict__ csr_src,
                        const uint2* __restrict__ Tin, const float4* __restrict__ f,
                        const float* __restrict__ dinv, const float* __restrict__ lam,
                        float4* __restrict__ X1, uint2* __restrict__ Tout, int n) {
    int v = blockIdx.x * 8 + threadIdx.y;
    if (v >= n) return;
    int lane = threadIdx.x;
    int g = lane >> 3, c = lane & 7;
    int beg = rs[v], end = rs[v + 1];
    float4 acc = row_sum4h(beg, end, csr_src, Tin, g, c);
    if (g == 0) {
        float r = 2.0f / lam[0];
        float dv = dinv[v];
        float4 f4 = __ldg(f + (size_t)v * 8 + c);
        float4 x1;
        x1.x = -r * acc.x * dv + (r - 1.0f) * f4.x;
        x1.y = -r * acc.y * dv + (r - 1.0f) * f4.y;
        x1.z = -r * acc.z * dv + (r - 1.0f) * f4.z;
        x1.w = -r * acc.w * dv + (r - 1.0f) * f4.w;
        X1[(size_t)v * 8 + c] = x1;
        float4 t;
        t.x = x1.x * dv; t.y = x1.y * dv; t.z = x1.z * dv; t.w = x1.w * dv;
        Tout[(size_t)v * 8 + c] = f4_to_h4(t);
    }
}

// X2 = -2r*acc*dv + 2(r-1)*X1 - f
__global__ void k_chebB(const int* __restrict__ rs, const int* __restrict__ csr_src,
                        const uint2* __restrict__ Tin, const float4* __restrict__ X1,
                        const float4* __restrict__ f, const float* __restrict__ dinv,
                        const float* __restrict__ lam, float4* __restrict__ X2, int n) {
    int v = blockIdx.x * 8 + threadIdx.y;
    if (v >= n) return;
    int lane = threadIdx.x;
    int g = lane >> 3, c = lane & 7;
    int beg = rs[v], end = rs[v + 1];
    float4 acc = row_sum4h(beg, end, csr_src, Tin, g, c);
    if (g == 0) {
        float r = 2.0f / lam[0];
        float dv = dinv[v];
        float4 x1 = __ldg(X1 + (size_t)v * 8 + c);
        float4 f4 = __ldg(f + (size_t)v * 8 + c);
        float4 o;
        o.x = -2.0f * r * acc.x * dv + 2.0f * (r - 1.0f) * x1.x - f4.x;
        o.y = -2.0f * r * acc.y * dv + 2.0f * (r - 1.0f) * x1.y - f4.y;
        o.z = -2.0f * r * acc.z * dv + 2.0f * (r - 1.0f) * x1.z - f4.z;
        o.w = -2.0f * r * acc.w * dv + 2.0f * (r - 1.0f) * x1.w - f4.w;
        X2[(size_t)v * 8 + c] = o;
    }
}

// out = leaky_relu([X0,X1,X2] @ W + b, 0.01); optionally Tout_h = half(out*dinv)
__global__ void k_cheb_linear(const float* __restrict__ X0, const float* __restrict__ X1,
                              const float* __restrict__ X2, const float* __restrict__ W,
                              const float* __restrict__ b, const float* __restrict__ dinv,
                              float* __restrict__ out, __half* __restrict__ Tout, int n) {
    __shared__ float sW[96 * 32];
    __shared__ float sb[32];
    int t = threadIdx.y * 32 + threadIdx.x;
    for (int i = t; i < 96 * 32; i += 256) sW[i] = W[i];
    if (t < 32) sb[t] = b[t];
    __syncthreads();
    int node = blockIdx.x * 8 + threadIdx.y;
    if (node >= n) return;
    int col = threadIdx.x;
    float s = sb[col];
    const float* x0 = X0 + (size_t)node * ND;
    const float* x1 = X1 + (size_t)node * ND;
    const float* x2 = X2 + (size_t)node * ND;
#pragma unroll
    for (int j = 0; j < 32; j++) s += x0[j] * sW[j * 32 + col];
#pragma unroll
    for (int j = 0; j < 32; j++) s += x1[j] * sW[(32 + j) * 32 + col];
#pragma unroll
    for (int j = 0; j < 32; j++) s += x2[j] * sW[(64 + j) * 32 + col];
    s = leaky(s, 0.01f);
    out[(size_t)node * ND + col] = s;
    if (Tout) Tout[(size_t)node * ND + col] = __float2half(s * dinv[node]);
}

// fs = h@Ws+bs ; fd = h@Wd+bd
__global__ void k_fsfd(const float* __restrict__ h, const float* __restrict__ Ws,
                       const float* __restrict__ bs, const float* __restrict__ Wd,
                       const float* __restrict__ bd, float* __restrict__ fs,
                       float* __restrict__ fd, int n) {
    __shared__ float sWs[32 * 32], sWd[32 * 32], sbs[32], sbd[32];
    int t = threadIdx.y * 32 + threadIdx.x;
    for (int i = t; i < 1024; i += 256) { sWs[i] = Ws[i]; sWd[i] = Wd[i]; }
    if (t < 32) { sbs[t] = bs[t]; sbd[t] = bd[t]; }
    __syncthreads();
    int node = blockIdx.x * 8 + threadIdx.y;
    if (node >= n) return;
    int col = threadIdx.x;
    float a = sbs[col], c = sbd[col];
    const float* hr = h + (size_t)node * ND;
#pragma unroll
    for (int j = 0; j < 32; j++) {
        float x = hr[j];
        a += x * sWs[j * 32 + col];
        c += x * sWd[j * 32 + col];
    }
    fs[(size_t)node * ND + col] = a;
    fd[(size_t)node * ND + col] = c;
}

// ---------------------------------------------------------------------------
// fused GATv2: one CSR pass, online softmax, 4 edges x 8 lanes per warp
// ---------------------------------------------------------------------------
__device__ __forceinline__ float edge_logit(float4 f0, float4 fd4, float4 w) {
    float t = leaky(f0.x + fd4.x, 0.2f) * w.x + leaky(f0.y + fd4.y, 0.2f) * w.y +
              leaky(f0.z + fd4.z, 0.2f) * w.z + leaky(f0.w + fd4.w, 0.2f) * w.w;
    t += __shfl_xor_sync(0xffffffffu, t, 1);
    t += __shfl_xor_sync(0xffffffffu, t, 2);
    t += __shfl_xor_sync(0xffffffffu, t, 4);
    return t;
}

__global__ void k_gat(const int* __restrict__ rs, const int* __restrict__ csr_src,
                      const float4* __restrict__ fs, const float4* __restrict__ fd,
                      const float4* __restrict__ attn, float4* __restrict__ out, int n) {
    int v = blockIdx.x * 8 + threadIdx.y;
    if (v >= n) return;
    int lane = threadIdx.x;
    int g = lane >> 3, c = lane & 7;
    int beg = rs[v], end = rs[v + 1];
    float4 fd4 = __ldg(fd + (size_t)v * 8 + c);
    float4 w = __ldg(attn + c);
    float m = -3.0e38f, den = 0.0f;
    float4 acc = make_float4(0.f, 0.f, 0.f, 0.f);
    int base = beg;
    for (; base + 8 <= end; base += 8) {
        int s0 = __ldg(csr_src + base + g);
        int s1 = __ldg(csr_src + base + 4 + g);
        float4 f0 = __ldg(fs + (size_t)s0 * 8 + c);
        float4 f1 = __ldg(fs + (size_t)s1 * 8 + c);
        float t0 = edge_logit(f0, fd4, w);
        float t1 = edge_logit(f1, fd4, w);
        float mn = fmaxf(m, t0);
        float sc = __expf(m - mn);
        float e = __expf(t0 - mn);
        den = den * sc + e;
        acc.x = acc.x * sc + f0.x * e;
        acc.y = acc.y * sc + f0.y * e;
        acc.z = acc.z * sc + f0.z * e;
        acc.w = acc.w * sc + f0.w * e;
        m = mn;
        mn = fmaxf(m, t1);
        sc = __expf(m - mn);
        e = __expf(t1 - mn);
        den = den * sc + e;
        acc.x = acc.x * sc + f1.x * e;
        acc.y = acc.y * sc + f1.y * e;
        acc.z = acc.z * sc + f1.z * e;
        acc.w = acc.w * sc + f1.w * e;
        m = mn;
    }
    for (; base < end; base += 4) {
        int p = base + g;
        bool valid = p < end;
        int s0 = valid ? __ldg(csr_src + p) : 0;
        float4 f0 = __ldg(fs + (size_t)s0 * 8 + c);
        float t0 = edge_logit(f0, fd4, w);  // all lanes participate in shfl
        if (valid) {
            float mn = fmaxf(m, t0);
            float sc = __expf(m - mn);
            float e = __expf(t0 - mn);
            den = den * sc + e;
            acc.x = acc.x * sc + f0.x * e;
            acc.y = acc.y * sc + f0.y * e;
            acc.z = acc.z * sc + f0.z * e;
            acc.w = acc.w * sc + f0.w * e;
            m = mn;
        }
    }
    // merge the 4 groups' online-softmax states
    float M = m;
    M = fmaxf(M, __shfl_xor_sync(0xffffffffu, M, 8));
    M = fmaxf(M, __shfl_xor_sync(0xffffffffu, M, 16));
    float sc = __expf(m - M);
    den *= sc;
    acc.x *= sc; acc.y *= sc; acc.z *= sc; acc.w *= sc;
#pragma unroll
    for (int o = 8; o <= 16; o <<= 1) {
        den   += __shfl_xor_sync(0xffffffffu, den,   o);
        acc.x += __shfl_xor_sync(0xffffffffu, acc.x, o);
        acc.y += __shfl_xor_sync(0xffffffffu, acc.y, o);
        acc.z += __shfl_xor_sync(0xffffffffu, acc.z, o);
        acc.w += __shfl_xor_sync(0xffffffffu, acc.w, o);
    }
    if (g == 0) {
        float inv = (den > 0.0f) ? 1.0f / den : 0.0f;
        float4 o;
        o.x = leaky(acc.x * inv, 0.01f);
        o.y = leaky(acc.y * inv, 0.01f);
        o.z = leaky(acc.z * inv, 0.01f);
        o.w = leaky(acc.w * inv, 0.01f);
        out[(size_t)v * 8 + c] = o;
    }
}

// ---------------------------------------------------------------------------
// launch
// ---------------------------------------------------------------------------
extern "C" void kernel_launch(void* const* d_in, const int* in_sizes, int n_in,
                              void* d_out, int out_size) {
    const int*   src  = (const int*)d_in[0];
    const int*   dst  = (const int*)d_in[1];
    const float* emb  = (const float*)d_in[2];
    const float* lam  = (const float*)d_in[3];
    const float* chW  = (const float*)d_in[4];
    const float* chb  = (const float*)d_in[5];
    const float* Ws   = (const float*)d_in[6];
    const float* bs   = (const float*)d_in[7];
    const float* Wd   = (const float*)d_in[8];
    const float* bd   = (const float*)d_in[9];
    const float* attn = (const float*)d_in[10];

    const int E = in_sizes[0];
    const int n = in_sizes[2] / ND;

    float* base = nullptr;
    cudaGetSymbolAddress((void**)&base, g_buf);

    float*  X1      = base;
    float*  X2      = base + 1 * SLOT;
    float*  h1      = base + 2 * SLOT;
    float*  h2      = base + 3 * SLOT;
    float*  fs      = base + 4 * SLOT;
    float*  fd      = base + 5 * SLOT;
    __half* T0h     = (__half*)(base + 6 * SLOT);
    __half* T1h     = (__half*)(base + 6 * SLOT + SLOT / 2);
    int*    csr_src = (int*)(base + 7 * SLOT);
    float*  tail    = base + 7 * SLOT + MAXE;
    int*    deg     = (int*)tail;
    int*    rs      = (int*)(tail + MAXN);          // N+1
    int*    cursor  = (int*)(tail + 2 * MAXN + 64);
    float*  dinv    = tail + 3 * MAXN + 64;
    int*    blk     = (int*)(tail + 4 * MAXN + 64);

    const int nt = 256;
    auto g = [&](long x) { return (int)((x + nt - 1) / nt); };
    const int gV4   = g((long)n * 8);
    const int gEdge = g((long)E);
    const int gNW   = (n + 7) / 8;
    dim3 bNW(32, 8);
    const int nb = (n + 1023) / 1024;

    // --- CSR build ---
    k_zero_i<<<g(n), nt>>>(deg, n);
    k_deg<<<gEdge, nt>>>(dst, deg, E);
    k_scan1<<<nb, 1024>>>(deg, rs, blk, n);
    k_scan2<<<1, 128>>>(blk, nb);
    k_scan3<<<g(n), nt>>>(rs, cursor, blk, deg, dinv, n, E);
    k_fill<<<gEdge, nt>>>(src, dst, cursor, csr_src, E);

    // --- ChebConv 1 (input = embedding) ---
    k_prescale<<<gV4, nt>>>((const float4*)emb, dinv, (uint2*)T0h, n);
    k_chebA<<<gNW, bNW>>>(rs, csr_src, (const uint2*)T0h, (const float4*)emb,
                          dinv, lam, (float4*)X1, (uint2*)T1h, n);
    k_chebB<<<gNW, bNW>>>(rs, csr_src, (const uint2*)T1h, (const float4*)X1,
                          (const float4*)emb, dinv, lam, (float4*)X2, n);
    k_cheb_linear<<<gNW, bNW>>>(emb, X1, X2, chW, chb, dinv, h1, T0h, n); // T0h = h1*dinv

    // --- ChebConv 2 (input = h1) ---
    k_chebA<<<gNW, bNW>>>(rs, csr_src, (const uint2*)T0h, (const float4*)h1,
                          dinv, lam, (float4*)X1, (uint2*)T1h, n);
    k_chebB<<<gNW, bNW>>>(rs, csr_src, (const uint2*)T1h, (const float4*)X1,
                          (const float4*)h1, dinv, lam, (float4*)X2, n);
    k_cheb_linear<<<gNW, bNW>>>(h1, X1, X2, chW, chb, dinv, h2, nullptr, n);

    // --- GATv2 (fused single pass) ---
    k_fsfd<<<gNW, bNW>>>(h2, Ws, bs, Wd, bd, fs, fd, n);
    k_gat<<<gNW, bNW>>>(rs, csr_src, (const float4*)fs, (const float4*)fd,
                        (const float4*)attn, (float4*)d_out, n);
}

// round 8
// speedup vs baseline: 1.4787x; 1.1938x over previous
#include <cuda_runtime.h>
#include <cuda_fp16.h>

#define ND 32
#define MAXN 100000
#define MAXE 1600000

static constexpr size_t SLOT = (size_t)MAXN * ND;

// Scratch arena (floats):
//  X1,h1,h2,fd : 4 * SLOT fp32
//  T0h,T1h,fsh : 3 * SLOT/2 (fp16 rows)
//  csr_src : MAXE int
//  tail: deg(N), rs(N+1), cursor(N), dinv(N), blk(128)
__device__ __align__(256) float g_buf[6 * SLOT + (size_t)MAXE + 6 * (size_t)MAXN + 2048];

__device__ __forceinline__ float leaky(float x, float s) {
    return x > 0.0f ? x : s * x;
}
__device__ __forceinline__ uint2 f4_to_h4(float4 v) {
    __half2 a = __floats2half2_rn(v.x, v.y);
    __half2 b = __floats2half2_rn(v.z, v.w);
    uint2 r;
    r.x = *(unsigned*)&a;
    r.y = *(unsigned*)&b;
    return r;
}
__device__ __forceinline__ float4 h4_to_f4(uint2 u) {
    __half2 a = *(__half2*)&u.x;
    __half2 b = *(__half2*)&u.y;
    float2 fa = __half22float2(a), fb = __half22float2(b);
    return make_float4(fa.x, fa.y, fb.x, fb.y);
}

// ---------------------------------------------------------------------------
// degree + scan + CSR fill
// ---------------------------------------------------------------------------
__global__ void k_zero_i(int* __restrict__ p, int n) {
    int i = blockIdx.x * blockDim.x + threadIdx.x;
    if (i < n) p[i] = 0;
}

__global__ void k_deg(const int* __restrict__ dst, int* __restrict__ deg, int E) {
    int e = blockIdx.x * blockDim.x + threadIdx.x;
    if (e < E) atomicAdd(&deg[dst[e]], 1);
}

__global__ void k_scan1(const int* __restrict__ deg, int* __restrict__ rs,
                        int* __restrict__ blk, int n) {
    __shared__ int sh[1024];
    int i = blockIdx.x * 1024 + threadIdx.x;
    int v = (i < n) ? deg[i] : 0;
    sh[threadIdx.x] = v;
    __syncthreads();
#pragma unroll
    for (int o = 1; o < 1024; o <<= 1) {
        int t = (threadIdx.x >= o) ? sh[threadIdx.x - o] : 0;
        __syncthreads();
        sh[threadIdx.x] += t;
        __syncthreads();
    }
    if (i < n) rs[i] = sh[threadIdx.x] - v;
    if (threadIdx.x == 1023) blk[blockIdx.x] = sh[1023];
}

__global__ void k_scan2(int* __restrict__ blk, int nb) {
    __shared__ int sh[128];
    int t = threadIdx.x;
    int v = (t < nb) ? blk[t] : 0;
    sh[t] = v;
    __syncthreads();
#pragma unroll
    for (int o = 1; o < 128; o <<= 1) {
        int x = (t >= o) ? sh[t - o] : 0;
        __syncthreads();
        sh[t] += x;
        __syncthreads();
    }
    if (t < nb) blk[t] = sh[t] - v;
}

__global__ void k_scan3(int* __restrict__ rs, int* __restrict__ cursor,
                        const int* __restrict__ blk, const int* __restrict__ deg,
                        float* __restrict__ dinv, int n, int E) {
    int i = blockIdx.x * blockDim.x + threadIdx.x;
    if (i < n) {
        int v = rs[i] + blk[i >> 10];
        rs[i] = v;
        cursor[i] = v;
        dinv[i] = rsqrtf(fmaxf((float)deg[i], 1.0f));
    }
    if (i == 0) rs[n] = E;
}

__global__ void k_fill(const int* __restrict__ src, const int* __restrict__ dst,
                       int* __restrict__ cursor, int* __restrict__ csr_src, int E) {
    int e = blockIdx.x * blockDim.x + threadIdx.x;
    if (e >= E) return;
    int p = atomicAdd(&cursor[dst[e]], 1);
    csr_src[p] = src[e];
}

// ---------------------------------------------------------------------------
// Cheb kernels
// ---------------------------------------------------------------------------
// T0h = half(f * dinv)
__global__ void k_prescale(const float4* __restrict__ f, const float* __restrict__ dinv,
                           uint2* __restrict__ Th, int n) {
    int i = blockIdx.x * blockDim.x + threadIdx.x;
    if (i >= n * 8) return;
    float dv = dinv[i >> 3];
    float4 v = f[i];
    v.x *= dv; v.y *= dv; v.z *= dv; v.w *= dv;
    Th[i] = f4_to_h4(v);
}

// warp-per-node CSR row sum over fp16 rows: 4 edges x 8 lanes, fp32 accum
__device__ __forceinline__ float4 row_sum4h(int beg, int end,
                                            const int* __restrict__ csr_src,
                                            const uint2* __restrict__ Th,
                                            int g, int c) {
    float4 acc = make_float4(0.f, 0.f, 0.f, 0.f);
    int base = beg;
    for (; base + 8 <= end; base += 8) {
        int i0 = __ldg(csr_src + base + g);
        int i1 = __ldg(csr_src + base + 4 + g);
        float4 v0 = h4_to_f4(__ldg(Th + (size_t)i0 * 8 + c));
        float4 v1 = h4_to_f4(__ldg(Th + (size_t)i1 * 8 + c));
        acc.x += v0.x + v1.x;
        acc.y += v0.y + v1.y;
        acc.z += v0.z + v1.z;
        acc.w += v0.w + v1.w;
    }
    for (; base < end; base += 4) {
        int p = base + g;
        if (p < end) {
            int i0 = __ldg(csr_src + p);
            float4 v0 = h4_to_f4(__ldg(Th + (size_t)i0 * 8 + c));
            acc.x += v0.x; acc.y += v0.y; acc.z += v0.z; acc.w += v0.w;
        }
    }
#pragma unroll
    for (int o = 8; o <= 16; o <<= 1) {
        acc.x += __shfl_xor_sync(0xffffffffu, acc.x, o);
        acc.y += __shfl_xor_sync(0xffffffffu, acc.y, o);
        acc.z += __shfl_xor_sync(0xffffffffu, acc.z, o);
        acc.w += __shfl_xor_sync(0xffffffffu, acc.w, o);
    }
    return acc;
}

// X1 = -r*acc*dv + (r-1)*f; T1h = half(X1*dv)
__global__ void k_chebA(const int* __restrict__ rs, const int* __restrict__ csr_src,
                        const uint2* __restrict__ Tin, const float4* __restrict__ f,
                        const float* __restrict__ dinv, const float* __restrict__ lam,
                        float4* __restrict__ X1, uint2* __restrict__ Tout, int n) {
    int v = blockIdx.x * 8 + threadIdx.y;
    if (v >= n) return;
    int lane = threadIdx.x;
    int g = lane >> 3, c = lane & 7;
    int beg = rs[v], end = rs[v + 1];
    float4 acc = row_sum4h(beg, end, csr_src, Tin, g, c);
    if (g == 0) {
        float r = 2.0f / lam[0];
        float dv = dinv[v];
        float4 f4 = __ldg(f + (size_t)v * 8 + c);
        float4 x1;
        x1.x = -r * acc.x * dv + (r - 1.0f) * f4.x;
        x1.y = -r * acc.y * dv + (r - 1.0f) * f4.y;
        x1.z = -r * acc.z * dv + (r - 1.0f) * f4.z;
        x1.w = -r * acc.w * dv + (r - 1.0f) * f4.w;
        X1[(size_t)v * 8 + c] = x1;
        float4 t;
        t.x = x1.x * dv; t.y = x1.y * dv; t.z = x1.z * dv; t.w = x1.w * dv;
        Tout[(size_t)v * 8 + c] = f4_to_h4(t);
    }
}

// Fused: acc = L-gather(T1h); X2 = -2r*acc*dv + 2(r-1)*X1 - f;
// out = leaky([X0,X1,X2] @ W + b); optional Tout_h = half(out*dinv)
__global__ void k_chebBL(const int* __restrict__ rs, const int* __restrict__ csr_src,
                         const uint2* __restrict__ Tin, const float4* __restrict__ X1,
                         const float4* __restrict__ f, const float* __restrict__ dinv,
                         const float* __restrict__ lam, const float* __restrict__ W,
                         const float* __restrict__ b, float* __restrict__ out,
                         __half* __restrict__ Tout, int n) {
    __shared__ float sW[96 * 32];
    __shared__ float sb[32];
    __shared__ float sX[8][96];
    int t = threadIdx.y * 32 + threadIdx.x;
    for (int i = t; i < 96 * 32; i += 256) sW[i] = W[i];
    if (t < 32) sb[t] = b[t];
    __syncthreads();

    int v = blockIdx.x * 8 + threadIdx.y;
    if (v >= n) return;
    int lane = threadIdx.x;
    int g = lane >> 3, c = lane & 7;
    int beg = rs[v], end = rs[v + 1];
    float4 acc = row_sum4h(beg, end, csr_src, Tin, g, c);
    if (g == 0) {
        float r = 2.0f / lam[0];
        float dv = dinv[v];
        float4 x1 = __ldg(X1 + (size_t)v * 8 + c);
        float4 f4 = __ldg(f + (size_t)v * 8 + c);
        float4 x2;
        x2.x = -2.0f * r * acc.x * dv + 2.0f * (r - 1.0f) * x1.x - f4.x;
        x2.y = -2.0f * r * acc.y * dv + 2.0f * (r - 1.0f) * x1.y - f4.y;
        x2.z = -2.0f * r * acc.z * dv + 2.0f * (r - 1.0f) * x1.z - f4.z;
        x2.w = -2.0f * r * acc.w * dv + 2.0f * (r - 1.0f) * x1.w - f4.w;
        // stage [X0 | X1 | X2] row into shared
        float* sx = sX[threadIdx.y];
        sx[c * 4 + 0] = f4.x;  sx[c * 4 + 1] = f4.y;
        sx[c * 4 + 2] = f4.z;  sx[c * 4 + 3] = f4.w;
        sx[32 + c * 4 + 0] = x1.x;  sx[32 + c * 4 + 1] = x1.y;
        sx[32 + c * 4 + 2] = x1.z;  sx[32 + c * 4 + 3] = x1.w;
        sx[64 + c * 4 + 0] = x2.x;  sx[64 + c * 4 + 1] = x2.y;
        sx[64 + c * 4 + 2] = x2.z;  sx[64 + c * 4 + 3] = x2.w;
    }
    __syncwarp();
    // GEMV: col = lane
    const float* sx = sX[threadIdx.y];
    float s = sb[lane];
#pragma unroll
    for (int j = 0; j < 96; j++) s += sx[j] * sW[j * 32 + lane];
    s = leaky(s, 0.01f);
    out[(size_t)v * ND + lane] = s;
    if (Tout) Tout[(size_t)v * ND + lane] = __float2half(s * dinv[v]);
}

// fs_h = half(h@Ws+bs) ; fd = h@Wd+bd
__global__ void k_fsfd(const float* __restrict__ h, const float* __restrict__ Ws,
                       const float* __restrict__ bs, const float* __restrict__ Wd,
                       const float* __restrict__ bd, __half* __restrict__ fsh,
                       float* __restrict__ fd, int n) {
    __shared__ float sWs[32 * 32], sWd[32 * 32], sbs[32], sbd[32];
    int t = threadIdx.y * 32 + threadIdx.x;
    for (int i = t; i < 1024; i += 256) { sWs[i] = Ws[i]; sWd[i] = Wd[i]; }
    if (t < 32) { sbs[t] = bs[t]; sbd[t] = bd[t]; }
    __syncthreads();
    int node = blockIdx.x * 8 + threadIdx.y;
    if (node >= n) return;
    int col = threadIdx.x;
    float a = sbs[col], c = sbd[col];
    const float* hr = h + (size_t)node * ND;
#pragma unroll
    for (int j = 0; j < 32; j++) {
        float x = hr[j];
        a += x * sWs[j * 32 + col];
        c += x * sWd[j * 32 + col];
    }
    fsh[(size_t)node * ND + col] = __float2half(a);
    fd[(size_t)node * ND + col] = c;
}

// ---------------------------------------------------------------------------
// fused GATv2: one CSR pass, online softmax, 4 edges x 8 lanes per warp
// fs rows in fp16
// ---------------------------------------------------------------------------
__device__ __forceinline__ float edge_logit(float4 f0, float4 fd4, float4 w) {
    float t = leaky(f0.x + fd4.x, 0.2f) * w.x + leaky(f0.y + fd4.y, 0.2f) * w.y +
              leaky(f0.z + fd4.z, 0.2f) * w.z + leaky(f0.w + fd4.w, 0.2f) * w.w;
    t += __shfl_xor_sync(0xffffffffu, t, 1);
    t += __shfl_xor_sync(0xffffffffu, t, 2);
    t += __shfl_xor_sync(0xffffffffu, t, 4);
    return t;
}

__global__ void k_gat(const int* __restrict__ rs, const int* __restrict__ csr_src,
                      const uint2* __restrict__ fsh, const float4* __restrict__ fd,
                      const float4* __restrict__ attn, float4* __restrict__ out, int n) {
    int v = blockIdx.x * 8 + threadIdx.y;
    if (v >= n) return;
    int lane = threadIdx.x;
    int g = lane >> 3, c = lane & 7;
    int beg = rs[v], end = rs[v + 1];
    float4 fd4 = __ldg(fd + (size_t)v * 8 + c);
    float4 w = __ldg(attn + c);
    float m = -3.0e38f, den = 0.0f;
    float4 acc = make_float4(0.f, 0.f, 0.f, 0.f);
    int base = beg;
    for (; base + 8 <= end; base += 8) {
        int s0 = __ldg(csr_src + base + g);
        int s1 = __ldg(csr_src + base + 4 + g);
        float4 f0 = h4_to_f4(__ldg(fsh + (size_t)s0 * 8 + c));
        float4 f1 = h4_to_f4(__ldg(fsh + (size_t)s1 * 8 + c));
        float t0 = edge_logit(f0, fd4, w);
        float t1 = edge_logit(f1, fd4, w);
        float mn = fmaxf(m, t0);
        float sc = __expf(m - mn);
        float e = __expf(t0 - mn);
        den = den * sc + e;
        acc.x = acc.x * sc + f0.x * e;
        acc.y = acc.y * sc + f0.y * e;
        acc.z = acc.z * sc + f0.z * e;
        acc.w = acc.w * sc + f0.w * e;
        m = mn;
        mn = fmaxf(m, t1);
        sc = __expf(m - mn);
        e = __expf(t1 - mn);
        den = den * sc + e;
        acc.x = acc.x * sc + f1.x * e;
        acc.y = acc.y * sc + f1.y * e;
        acc.z = acc.z * sc + f1.z * e;
        acc.w = acc.w * sc + f1.w * e;
        m = mn;
    }
    for (; base < end; base += 4) {
        int p = base + g;
        bool valid = p < end;
        int s0 = valid ? __ldg(csr_src + p) : 0;
        float4 f0 = h4_to_f4(__ldg(fsh + (size_t)s0 * 8 + c));
        float t0 = edge_logit(f0, fd4, w);  // all lanes participate in shfl
        if (valid) {
            float mn = fmaxf(m, t0);
            float sc = __expf(m - mn);
            float e = __expf(t0 - mn);
            den = den * sc + e;
            acc.x = acc.x * sc + f0.x * e;
            acc.y = acc.y * sc + f0.y * e;
            acc.z = acc.z * sc + f0.z * e;
            acc.w = acc.w * sc + f0.w * e;
            m = mn;
        }
    }
    // merge the 4 groups' online-softmax states
    float M = m;
    M = fmaxf(M, __shfl_xor_sync(0xffffffffu, M, 8));
    M = fmaxf(M, __shfl_xor_sync(0xffffffffu, M, 16));
    float sc = __expf(m - M);
    den *= sc;
    acc.x *= sc; acc.y *= sc; acc.z *= sc; acc.w *= sc;
#pragma unroll
    for (int o = 8; o <= 16; o <<= 1) {
        den   += __shfl_xor_sync(0xffffffffu, den,   o);
        acc.x += __shfl_xor_sync(0xffffffffu, acc.x, o);
        acc.y += __shfl_xor_sync(0xffffffffu, acc.y, o);
        acc.z += __shfl_xor_sync(0xffffffffu, acc.z, o);
        acc.w += __shfl_xor_sync(0xffffffffu, acc.w, o);
    }
    if (g == 0) {
        float inv = (den > 0.0f) ? 1.0f / den : 0.0f;
        float4 o;
        o.x = leaky(acc.x * inv, 0.01f);
        o.y = leaky(acc.y * inv, 0.01f);
        o.z = leaky(acc.z * inv, 0.01f);
        o.w = leaky(acc.w * inv, 0.01f);
        out[(size_t)v * 8 + c] = o;
    }
}

// ---------------------------------------------------------------------------
// launch
// ---------------------------------------------------------------------------
extern "C" void kernel_launch(void* const* d_in, const int* in_sizes, int n_in,
                              void* d_out, int out_size) {
    const int*   src  = (const int*)d_in[0];
    const int*   dst  = (const int*)d_in[1];
    const float* emb  = (const float*)d_in[2];
    const float* lam  = (const float*)d_in[3];
    const float* chW  = (const float*)d_in[4];
    const float* chb  = (const float*)d_in[5];
    const float* Ws   = (const float*)d_in[6];
    const float* bs   = (const float*)d_in[7];
    const float* Wd   = (const float*)d_in[8];
    const float* bd   = (const float*)d_in[9];
    const float* attn = (const float*)d_in[10];

    const int E = in_sizes[0];
    const int n = in_sizes[2] / ND;

    float* base = nullptr;
    cudaGetSymbolAddress((void**)&base, g_buf);

    float*  X1      = base;
    float*  h1      = base + 1 * SLOT;
    float*  h2      = base + 2 * SLOT;
    float*  fd      = base + 3 * SLOT;
    __half* T0h     = (__half*)(base + 4 * SLOT);
    __half* T1h     = (__half*)(base + 4 * SLOT + SLOT / 2);
    __half* fsh     = (__half*)(base + 5 * SLOT);
    int*    csr_src = (int*)(base + 6 * SLOT);
    float*  tail    = base + 6 * SLOT + MAXE;
    int*    deg     = (int*)tail;
    int*    rs      = (int*)(tail + MAXN);          // N+1
    int*    cursor  = (int*)(tail + 2 * MAXN + 64);
    float*  dinv    = tail + 3 * MAXN + 64;
    int*    blk     = (int*)(tail + 4 * MAXN + 64);

    const int nt = 256;
    auto g = [&](long x) { return (int)((x + nt - 1) / nt); };
    const int gV4   = g((long)n * 8);
    const int gEdge = g((long)E);
    const int gNW   = (n + 7) / 8;
    dim3 bNW(32, 8);
    const int nb = (n + 1023) / 1024;

    // --- CSR build ---
    k_zero_i<<<g(n), nt>>>(deg, n);
    k_deg<<<gEdge, nt>>>(dst, deg, E);
    k_scan1<<<nb, 1024>>>(deg, rs, blk, n);
    k_scan2<<<1, 128>>>(blk, nb);
    k_scan3<<<g(n), nt>>>(rs, cursor, blk, deg, dinv, n, E);
    k_fill<<<gEdge, nt>>>(src, dst, cursor, csr_src, E);

    // --- ChebConv 1 (input = embedding) ---
    k_prescale<<<gV4, nt>>>((const float4*)emb, dinv, (uint2*)T0h, n);
    k_chebA<<<gNW, bNW>>>(rs, csr_src, (const uint2*)T0h, (const float4*)emb,
                          dinv, lam, (float4*)X1, (uint2*)T1h, n);
    k_chebBL<<<gNW, bNW>>>(rs, csr_src, (const uint2*)T1h, (const float4*)X1,
                           (const float4*)emb, dinv, lam, chW, chb, h1, T0h, n);

    // --- ChebConv 2 (input = h1; T0h = h1*dinv from above) ---
    k_chebA<<<gNW, bNW>>>(rs, csr_src, (const uint2*)T0h, (const float4*)h1,
                          dinv, lam, (float4*)X1, (uint2*)T1h, n);
    k_chebBL<<<gNW, bNW>>>(rs, csr_src, (const uint2*)T1h, (const float4*)X1,
                           (const float4*)h1, dinv, lam, chW, chb, h2, nullptr, n);

    // --- GATv2 (fused single pass, fp16 fs) ---
    k_fsfd<<<gNW, bNW>>>(h2, Ws, bs, Wd, bd, fsh, fd, n);
    k_gat<<<gNW, bNW>>>(rs, csr_src, (const uint2*)fsh, (const float4*)fd,
                        (const float4*)attn, (float4*)d_out, n);
}